// round 4
// baseline (speedup 1.0000x reference)
#include <cuda_runtime.h>

#define HH 512
#define WW 512
#define PD 16            // KS/2
#define RC 8             // rows per chunk == warps per block
#define RPB 64           // output rows per block
#define NT 256           // one thread per column PAIR
#define PITCH2 290       // float2 slots per array row (need 289)

__device__ __forceinline__ int gmap(int p) { return p + (p >> 3); }   // pair swizzle

__device__ __forceinline__ float frsqrt(float v) {
    float r;
    asm("rsqrt.approx.f32 %0, %1;" : "=f"(r) : "f"(v));
    return r;
}

__global__ __launch_bounds__(NT, 6)
void localnorm_v4(const float* __restrict__ x, float* __restrict__ out) {
    __shared__ float2 S2[RC][PITCH2];   // vertical sums of x   -> shifted prefix
    __shared__ float2 Q2[RC][PITCH2];   // vertical sums of x^2 -> shifted prefix

    const int t    = threadIdx.x;       // column pair index: cols 2t, 2t+1
    const int lane = t & 31;
    const int wid  = t >> 5;
    const int r0   = blockIdx.x * RPB;

    const float2* __restrict__ X2 = (const float2*)x   + (size_t)blockIdx.y * (HH * 256);
    float2* __restrict__       O2 = (float2*)out       + (size_t)blockIdx.y * (HH * 256);

    // ---- init vertical window: rows r0-16 .. r0+15 ----
    float2 vs = make_float2(0.f, 0.f), vq = make_float2(0.f, 0.f);
    for (int d = -PD; d < PD; d++) {
        int rr = abs(r0 + d);                          // lower reflect only
        float2 v = X2[(rr << 8) + t];
        vs.x += v.x;  vs.y += v.y;
        vq.x = fmaf(v.x, v.x, vq.x);
        vq.y = fmaf(v.y, v.y, vq.y);
    }

    const int slotA = gmap(t);
    // ---- phase-C per-thread constants ----
    const bool haveL   = (t >= 8);
    const bool leftE   = (t <= 7);                     // either column spills left
    const bool rightE1 = (t >= 248);                   // col 2t+1 spills right
    const bool rightE0 = (t >= 249);                   // col 2t   spills right
    const int  plo_idx = gmap(haveL ? (t - 8) : 0);
    const int  phi_idx = gmap((t + 8 < 256) ? (t + 8) : 256);
    const int  le_idx  = gmap(leftE   ? (8 - t)   : 0);
    const int  re_idx  = gmap(rightE1 ? (503 - t) : 0);
    const int  SLOT255 = gmap(255);                    // .y holds P[510]
    const float inv_n  = 1.f / 1024.f;

    #pragma unroll 1
    for (int chunk = 0; chunk < RPB / RC; chunk++) {
        const int ibase = r0 + chunk * RC;

        // ---- phase A: emit RC rows of vertical sums; slide window ----
        #pragma unroll
        for (int rr = 0; rr < RC; rr++) {
            S2[rr][slotA] = vs;
            Q2[rr][slotA] = vq;
            int i  = ibase + rr;
            int ru = i + PD; ru = (ru < HH) ? ru : (2 * HH - 2 - ru);
            int rd = abs(i - PD);
            float2 va = X2[(ru << 8) + t];
            float2 vb = X2[(rd << 8) + t];
            vs.x += va.x - vb.x;   vs.y += va.y - vb.y;
            vq.x = fmaf(va.x, va.x, fmaf(-vb.x, vb.x, vq.x));
            vq.y = fmaf(va.y, va.y, fmaf(-vb.y, vb.y, vq.y));
        }
        __syncthreads();

        // ---- phase B: warp w scans S2[w], Q2[w]; writes SHIFTED prefix ----
        // stored[pos] = P[pos-1]; lane l owns scalars 16l..16l+15 (float2 slots 9l..9l+7)
        {
            const int b = 9 * lane;
            #pragma unroll
            for (int a = 0; a < 2; a++) {
                float2* V = (a == 0) ? &S2[wid][0] : &Q2[wid][0];
                float run = 0.f;
                #pragma unroll
                for (int k = 0; k < 8; k++) { float2 v = V[b + k]; run += v.x + v.y; }
                float tot = run;
                #pragma unroll
                for (int s = 1; s < 32; s <<= 1) {
                    float u = __shfl_up_sync(0xffffffffu, tot, s);
                    if (lane >= s) tot += u;
                }
                float acc = tot - run;                 // exclusive offset
                float2 v = V[b];
                acc += v.x;                            // P[16l]
                if (lane == 0) V[b] = make_float2(0.f, acc);   // pos0 = P[-1] = 0
                else           V[b].y = acc;
                float ph = v.y;
                #pragma unroll
                for (int k = 1; k < 8; k++) {
                    v = V[b + k];
                    float p0 = acc + ph;               // P[16l+2k-1]
                    float p1 = p0 + v.x;               // P[16l+2k]
                    V[b + k] = make_float2(p0, p1);
                    acc = p1; ph = v.y;
                }
                V[b + 9].x = acc + ph;                 // P[16l+15] at pos 16l+16
            }
        }
        __syncthreads();

        // ---- phase C: boxes from shifted prefix; finalize 2 cols/thread ----
        const float2* Xc = X2 + (ibase << 8) + t;
        float2*       Oc = O2 + (ibase << 8) + t;
        #pragma unroll
        for (int rr = 0; rr < RC; rr++) {
            float2 pls = haveL ? S2[rr][plo_idx] : make_float2(0.f, 0.f);
            float2 plq = haveL ? Q2[rr][plo_idx] : make_float2(0.f, 0.f);
            float2 phs = S2[rr][phi_idx];
            float2 phq = Q2[rr][phi_idx];
            float h1s = rightE1 ? phs.x : phs.y;
            float h1q = rightE1 ? phq.x : phq.y;
            float bS0 = phs.x - pls.x,  bS1 = h1s - pls.y;
            float bQ0 = phq.x - plq.x,  bQ1 = h1q - plq.y;
            if (leftE) {
                float2 es = S2[rr][le_idx], eq = Q2[rr][le_idx];
                float p0s = S2[rr][0].y,    p0q = Q2[rr][0].y;       // P[0]
                bS0 += es.y - p0s;  bS1 += es.x - p0s;
                bQ0 += eq.y - p0q;  bQ1 += eq.x - p0q;
            }
            if (rightE1) {
                float2 es = S2[rr][re_idx], eq = Q2[rr][re_idx];
                float pTs = S2[rr][SLOT255].y, pTq = Q2[rr][SLOT255].y;  // P[510]
                if (rightE0) { bS0 += pTs - es.y;  bQ0 += pTq - eq.y; }
                bS1 += pTs - es.x;  bQ1 += pTq - eq.x;
            }
            float2 xc = Xc[rr << 8];
            float m0 = bS0 * inv_n,  m1 = bS1 * inv_n;
            float v0 = fabsf(fmaf(-m0, m0, bQ0 * inv_n));
            float v1 = fabsf(fmaf(-m1, m1, bQ1 * inv_n));
            float o0 = (xc.x - m0) * frsqrt(v0 + 1e-20f);
            float o1 = (xc.y - m1) * frsqrt(v1 + 1e-20f);
            o0 = fminf(fmaxf(o0, -6.f), 6.f);
            o1 = fminf(fmaxf(o1, -6.f), 6.f);
            Oc[rr << 8] = make_float2(o0, o1);
        }
        __syncthreads();                               // protect smem for next chunk
    }
}

extern "C" void kernel_launch(void* const* d_in, const int* in_sizes, int n_in,
                              void* d_out, int out_size) {
    const float* x = (const float*)d_in[0];
    float* out = (float*)d_out;
    const int n_img = in_sizes[0] / (HH * WW);         // 96

    dim3 grid(HH / RPB, n_img);                        // 8 x 96 = 768 blocks
    localnorm_v4<<<grid, NT>>>(x, out);
}

// round 5
// speedup vs baseline: 1.3041x; 1.3041x over previous
#include <cuda_runtime.h>

#define HH 512
#define WW 512
#define KS 32
#define PD 16            // KS/2
#define RC 8             // rows per chunk (16 scan arrays = 16 warps)
#define RPB 128          // output rows per block
#define NT 512           // one thread per real column
#define SPITCH 544       // f(c) = c + (c>>4) maps 0..511 -> 0..542; slot 543 = zero
#define ZSLOT 543

__device__ __forceinline__ float frsqrt(float v) {
    float r;
    asm("rsqrt.approx.f32 %0, %1;" : "=f"(r) : "f"(v));
    return r;
}

__global__ __launch_bounds__(NT, 3)
void localnorm_v5(const float* __restrict__ x, float* __restrict__ out) {
    __shared__ float sS[RC * SPITCH];   // vertical sums of x   -> in-place prefix
    __shared__ float sQ[RC * SPITCH];   // vertical sums of x^2 -> in-place prefix

    const int tid  = threadIdx.x;
    const int lane = tid & 31;
    const int wid  = tid >> 5;
    const int r0   = blockIdx.x * RPB;

    const float* __restrict__ X = x   + (size_t)blockIdx.y * (HH * WW);
    float* __restrict__       O = out + (size_t)blockIdx.y * (HH * WW);

    // zero the "P[-1]" slot once (never touched by phases A/B)
    if (tid < 2 * RC) {
        float* p = (tid < RC) ? sS : sQ;
        p[(tid & (RC - 1)) * SPITCH + ZSLOT] = 0.f;
    }

    // ---- init vertical window: rows r0-16 .. r0+15 (only lower reflect possible) ----
    float vs = 0.f, vq = 0.f;
    #pragma unroll
    for (int d = -PD; d < PD; d++) {
        int rr = abs(r0 + d);                    // numpy 'reflect', lower edge
        float v = X[(rr << 9) + tid];
        vs += v; vq = fmaf(v, v, vq);
    }

    const int fcol = tid + (tid >> 4);           // phase-A store slot
    const float inv_n = 1.f / (float)(KS * KS);

    // ---- phase-C per-thread constants (oc == tid) ----
    const int oc  = tid;
    int hi = oc + 15; if (hi > 511) hi = 511;
    const int fhi = hi + (hi >> 4);
    const int lo  = oc - 17;
    const int flo = (lo >= 0) ? (lo + (lo >> 4)) : ZSLOT;     // P[-1] == 0
    const bool leftE  = (oc <= 15);              // window spills past column 0
    const bool rightE = (oc >= 497);             // window spills past column 511
    const int fle  = leftE  ? ((16 - oc) + ((16 - oc) >> 4)) : 0;
    const int fre2 = rightE ? ((1006 - oc) + ((1006 - oc) >> 4)) : 0;

    #pragma unroll 1
    for (int chunk = 0; chunk < RPB / RC; chunk++) {
        const int ibase = r0 + chunk * RC;

        // ---- phase A: emit RC rows of vertical sums; slide the window ----
        #pragma unroll
        for (int rr = 0; rr < RC; rr++) {
            sS[rr * SPITCH + fcol] = vs;
            sQ[rr * SPITCH + fcol] = vq;
            int i  = ibase + rr;
            int ru = i + PD; ru = (ru < HH) ? ru : (2 * HH - 2 - ru);  // upper reflect only
            int rd = abs(i - PD);                                       // lower reflect only
            float va = X[(ru << 9) + tid];
            float vb = X[(rd << 9) + tid];
            vs += va - vb;
            vq = fmaf(va, va, fmaf(-vb, vb, vq));
        }
        __syncthreads();

        // ---- phase B: 16 warps, one (row,array) each; inclusive prefix over 512 ----
        {
            float* V = ((wid & 1) ? sQ : sS) + (wid >> 1) * SPITCH + lane * 17;
            float run = 0.f;
            #pragma unroll
            for (int k = 0; k < 16; k++) run += V[k];
            float tot = run;                     // warp-scan lane totals
            #pragma unroll
            for (int s = 1; s < 32; s <<= 1) {
                float u = __shfl_up_sync(0xffffffffu, tot, s);
                if (lane >= s) tot += u;
            }
            float acc = tot - run;               // exclusive offset
            #pragma unroll
            for (int k = 0; k < 16; k++) {
                acc += V[k];
                V[k] = acc;
            }
        }
        __syncthreads();

        // ---- phase C: box[oc] = P[hi]-P[lo] (+ reflected edge terms); finalize ----
        const float* Xc = X + (ibase << 9) + tid;
        float*       Oc = O + (ibase << 9) + tid;
        #pragma unroll
        for (int rr = 0; rr < RC; rr++) {
            const float* pS = sS + rr * SPITCH;
            const float* pQ = sQ + rr * SPITCH;
            float bS = pS[fhi] - pS[flo];
            float bQ = pQ[fhi] - pQ[flo];
            if (leftE)  { bS += pS[fle] - pS[0];    bQ += pQ[fle] - pQ[0]; }
            if (rightE) { bS += pS[541] - pS[fre2]; bQ += pQ[541] - pQ[fre2]; }
            float mean = bS * inv_n;
            float msq  = bQ * inv_n;
            float xc   = Xc[rr << 9];
            float var  = fabsf(fmaf(-mean, mean, msq));
            float r    = (xc - mean) * frsqrt(var + 1e-20f);
            r = fminf(fmaxf(r, -6.f), 6.f);
            Oc[rr << 9] = r;
        }
        __syncthreads();                          // protect sS/sQ for next phase A
    }
}

extern "C" void kernel_launch(void* const* d_in, const int* in_sizes, int n_in,
                              void* d_out, int out_size) {
    const float* x = (const float*)d_in[0];
    float* out = (float*)d_out;
    const int n_img = in_sizes[0] / (HH * WW);    // 96

    dim3 grid(HH / RPB, n_img);                   // 4 x 96 = 384 blocks
    localnorm_v5<<<grid, NT>>>(x, out);
}